// round 9
// baseline (speedup 1.0000x reference)
#include <cuda_runtime.h>
#include <cuda_fp16.h>
#include <cstdint>

#define F   128
#define NG  512
#define MAXN 100000
#define CAP 96

// ---- scratch (static device globals: allocation-free) ----
__device__ __half g_A[(size_t)MAXN * F];    // GEMM outputs (fp16)
__device__ float  g_B[(size_t)MAXN * F];    // aggregation outputs (fp32)
__device__ int    g_adj[(size_t)MAXN * CAP];
__device__ int    g_indeg[MAXN];
__device__ float  g_dinv[MAXN];
__device__ float  g_pool[NG * F];
__device__ float  g_cnt[NG];

// ============================ small kernels ============================
__global__ void k_init(int n) {
    int i = blockIdx.x * blockDim.x + threadIdx.x;
    if (i < n)       g_indeg[i] = 0;
    if (i < NG * F)  g_pool[i] = 0.0f;
    if (i < NG)      g_cnt[i] = 0.0f;
}

__global__ void k_scatter(const int* __restrict__ src, const int* __restrict__ dst,
                          int E, const int* __restrict__ batch, int n) {
    int i = blockIdx.x * blockDim.x + threadIdx.x;
    if (i < E) {
        int d = dst[i];
        int slot = atomicAdd(&g_indeg[d], 1);
        if (slot < CAP) g_adj[(size_t)d * CAP + slot] = src[i];
    }
    if (i < n) atomicAdd(&g_cnt[batch[i]], 1.0f);
}

__global__ void k_dinv(int n) {
    int i = blockIdx.x * blockDim.x + threadIdx.x;
    if (i < n) g_dinv[i] = rsqrtf((float)g_indeg[i] + 1.0f);
}

// ============================ persistent tf32 GEMM, W in registers ============================
// Y[M,128](fp16) = X[M,128](fp32) @ W[128,128](fp32)
// 8 warps; warp w: all 32 tile rows x 16 cols (col0 = w*16).
// B fragments (W) in 64 regs/thread, loaded once per persistent block.
// smem: two 32x132 X buffers (33792 B), cp.async double buffered.
#define XS_STRIDE 132
#define TROWS 32
#define XBUF (TROWS * XS_STRIDE)          // floats per buffer
#define SMEM_GEMM (2 * XBUF * 4)          // 33792 B

__device__ __forceinline__ uint32_t f2tf32(float v) {
    uint32_t u;
    asm("cvt.rna.tf32.f32 %0, %1;" : "=r"(u) : "f"(v));
    return u;
}
__device__ __forceinline__ uint32_t smem_u32(const void* p) {
    uint32_t a;
    asm("{ .reg .u64 t; cvta.to.shared.u64 t, %1; cvt.u32.u64 %0, t; }" : "=r"(a) : "l"(p));
    return a;
}
__device__ __forceinline__ void cp16(uint32_t dst, const void* src) {
    asm volatile("cp.async.ca.shared.global [%0], [%1], 16;" :: "r"(dst), "l"(src));
}

__global__ void __launch_bounds__(256, 2) k_gemm_tc(const float* __restrict__ X,
                                                    const float* __restrict__ W,
                                                    __half* __restrict__ Y,
                                                    int M, int ntiles) {
    extern __shared__ float sm[];
    int tid = threadIdx.x, wid = tid >> 5, lane = tid & 31;
    int gr = lane >> 2;          // 0..7
    int tg = lane & 3;           // 0..3
    int col0 = wid * 16;
    uint32_t xs_base = smem_u32(sm);

    // B fragments -> registers (once per persistent block), tf32-rounded
    float2 breg[16][2];
    #pragma unroll
    for (int ks = 0; ks < 16; ++ks)
        #pragma unroll
        for (int j = 0; j < 2; ++j) {
            int col = col0 + j * 8 + gr;
            breg[ks][j].x = __uint_as_float(f2tf32(W[(ks * 8 + tg) * 128 + col]));
            breg[ks][j].y = __uint_as_float(f2tf32(W[(ks * 8 + 4 + tg) * 128 + col]));
        }

    // prefetch first tile into buffer 0
    {
        int t0 = blockIdx.x;
        if (t0 < ntiles) {
            int row0 = t0 * TROWS;
            for (int g = tid; g < TROWS * 32; g += 256) {
                int r = g >> 5, c4 = g & 31;
                uint32_t dst = xs_base + (uint32_t)((r * XS_STRIDE + c4 * 4) * 4);
                if (row0 + r < M)
                    cp16(dst, (const float4*)X + (size_t)(row0 + r) * 32 + c4);
                else
                    asm volatile("st.shared.v4.b32 [%0], {%1,%1,%1,%1};" :: "r"(dst), "r"(0));
            }
        }
        asm volatile("cp.async.commit_group;");
    }

    int p = 0;
    for (int t = blockIdx.x; t < ntiles; t += gridDim.x, p ^= 1) {
        // prefetch next tile into other buffer
        int tn = t + gridDim.x;
        if (tn < ntiles) {
            int row0n = tn * TROWS;
            for (int g = tid; g < TROWS * 32; g += 256) {
                int r = g >> 5, c4 = g & 31;
                uint32_t dst = xs_base + (uint32_t)((((p ^ 1) * XBUF) + r * XS_STRIDE + c4 * 4) * 4);
                if (row0n + r < M)
                    cp16(dst, (const float4*)X + (size_t)(row0n + r) * 32 + c4);
                else
                    asm volatile("st.shared.v4.b32 [%0], {%1,%1,%1,%1};" :: "r"(dst), "r"(0));
            }
        }
        asm volatile("cp.async.commit_group;");
        asm volatile("cp.async.wait_group 1;");
        __syncthreads();

        const float* Xs = sm + p * XBUF;
        float c[2][2][4];
        #pragma unroll
        for (int a = 0; a < 2; ++a)
            #pragma unroll
            for (int b = 0; b < 2; ++b)
                #pragma unroll
                for (int k = 0; k < 4; ++k) c[a][b][k] = 0.f;

        const float* xa = Xs + gr * XS_STRIDE + tg;
        #pragma unroll
        for (int ks = 0; ks < 16; ++ks) {
            int k0 = ks * 8;
            uint32_t a0 = __float_as_uint(xa[k0]);
            uint32_t a1 = __float_as_uint(xa[8 * XS_STRIDE + k0]);
            uint32_t a2 = __float_as_uint(xa[k0 + 4]);
            uint32_t a3 = __float_as_uint(xa[8 * XS_STRIDE + k0 + 4]);
            uint32_t a4 = __float_as_uint(xa[16 * XS_STRIDE + k0]);
            uint32_t a5 = __float_as_uint(xa[24 * XS_STRIDE + k0]);
            uint32_t a6 = __float_as_uint(xa[16 * XS_STRIDE + k0 + 4]);
            uint32_t a7 = __float_as_uint(xa[24 * XS_STRIDE + k0 + 4]);
            #pragma unroll
            for (int j = 0; j < 2; ++j) {
                uint32_t b0 = __float_as_uint(breg[ks][j].x);
                uint32_t b1 = __float_as_uint(breg[ks][j].y);
                asm volatile(
                    "mma.sync.aligned.m16n8k8.row.col.f32.tf32.tf32.f32 "
                    "{%0,%1,%2,%3}, {%4,%5,%6,%7}, {%8,%9}, {%0,%1,%2,%3};"
                    : "+f"(c[0][j][0]), "+f"(c[0][j][1]), "+f"(c[0][j][2]), "+f"(c[0][j][3])
                    : "r"(a0), "r"(a1), "r"(a2), "r"(a3), "r"(b0), "r"(b1));
                asm volatile(
                    "mma.sync.aligned.m16n8k8.row.col.f32.tf32.tf32.f32 "
                    "{%0,%1,%2,%3}, {%4,%5,%6,%7}, {%8,%9}, {%0,%1,%2,%3};"
                    : "+f"(c[1][j][0]), "+f"(c[1][j][1]), "+f"(c[1][j][2]), "+f"(c[1][j][3])
                    : "r"(a4), "r"(a5), "r"(a6), "r"(a7), "r"(b0), "r"(b1));
            }
        }

        // epilogue: fp16 stores
        int row0 = t * TROWS;
        #pragma unroll
        for (int r2 = 0; r2 < 2; ++r2) {
            int r_top = row0 + r2 * 16 + gr;
            int r_bot = r_top + 8;
            #pragma unroll
            for (int j = 0; j < 2; ++j) {
                int col = col0 + j * 8 + tg * 2;
                if (r_top < M)
                    *(__half2*)(Y + (size_t)r_top * 128 + col) =
                        __float22half2_rn(make_float2(c[r2][j][0], c[r2][j][1]));
                if (r_bot < M)
                    *(__half2*)(Y + (size_t)r_bot * 128 + col) =
                        __float22half2_rn(make_float2(c[r2][j][2], c[r2][j][3]));
            }
        }
        __syncthreads();
    }
}

// ============================ aggregation (fp16 gather, warp per node) ============================
__device__ __forceinline__ void acc_row(float4& acc, const __half* H, int s, float nn, int lane) {
    uint2 u = ((const uint2*)(H + (size_t)s * F))[lane];
    __half2 h01 = *reinterpret_cast<__half2*>(&u.x);
    __half2 h23 = *reinterpret_cast<__half2*>(&u.y);
    float2 f01 = __half22float2(h01);
    float2 f23 = __half22float2(h23);
    acc.x += f01.x * nn; acc.y += f01.y * nn;
    acc.z += f23.x * nn; acc.w += f23.y * nn;
}

__global__ void k_agg(const __half* __restrict__ H, float* __restrict__ C,
                      const float* __restrict__ bias, int do_bias, int do_relu, int n) {
    int w = (blockIdx.x * blockDim.x + threadIdx.x) >> 5;
    int lane = threadIdx.x & 31;
    if (w >= n) return;
    int d = w;
    float dd = g_dinv[d];
    int cnt = g_indeg[d];
    if (cnt > CAP) cnt = CAP;

    float4 acc = make_float4(0.f, 0.f, 0.f, 0.f);
    acc_row(acc, H, d, dd * dd, lane);           // self loop

    const int* adj = g_adj + (size_t)d * CAP;
    int e = 0;
    for (; e + 4 <= cnt; e += 4) {
        int4 q = *(const int4*)(adj + e);
        float n0 = g_dinv[q.x] * dd;
        float n1 = g_dinv[q.y] * dd;
        float n2 = g_dinv[q.z] * dd;
        float n3 = g_dinv[q.w] * dd;
        acc_row(acc, H, q.x, n0, lane);
        acc_row(acc, H, q.y, n1, lane);
        acc_row(acc, H, q.z, n2, lane);
        acc_row(acc, H, q.w, n3, lane);
    }
    for (; e < cnt; ++e) {
        int s = adj[e];
        acc_row(acc, H, s, g_dinv[s] * dd, lane);
    }

    if (do_bias) {
        float4 bv = ((const float4*)bias)[lane];
        acc.x += bv.x; acc.y += bv.y; acc.z += bv.z; acc.w += bv.w;
    }
    if (do_relu) {
        acc.x = fmaxf(acc.x, 0.f); acc.y = fmaxf(acc.y, 0.f);
        acc.z = fmaxf(acc.z, 0.f); acc.w = fmaxf(acc.w, 0.f);
    }
    ((float4*)(C + (size_t)d * F))[lane] = acc;
}

// ---- segmented mean-pool accumulate (batch sorted): adds b2 here ----
__global__ void k_pool(const float* __restrict__ C, const float* __restrict__ b2,
                       const int* __restrict__ batch, int n) {
    int f = threadIdx.x;
    int n0 = blockIdx.x * 32;
    float bb = b2[f];
    int cur = -1;
    float acc = 0.f;
    for (int j = 0; j < 32; ++j) {
        int node = n0 + j;
        if (node >= n) break;
        int g = batch[node];
        if (g != cur) {
            if (cur >= 0) atomicAdd(&g_pool[cur * F + f], acc);
            cur = g; acc = 0.f;
        }
        acc += C[(size_t)node * F + f] + bb;
    }
    if (cur >= 0) atomicAdd(&g_pool[cur * F + f], acc);
}

__global__ void k_final(const float* __restrict__ Wl, const float* __restrict__ bl,
                        float* __restrict__ out) {
    int g = blockIdx.x;
    int f = threadIdx.x;
    __shared__ float sh[F];
    float c = fmaxf(g_cnt[g], 1.0f);
    sh[f] = g_pool[g * F + f] / c * Wl[f];
    __syncthreads();
    for (int o = 64; o > 0; o >>= 1) {
        if (f < o) sh[f] += sh[f + o];
        __syncthreads();
    }
    if (f == 0) out[g] = sh[0] + bl[0];
}

// ============================ launcher ============================
extern "C" void kernel_launch(void* const* d_in, const int* in_sizes, int n_in,
                              void* d_out, int out_size) {
    const float* x     = (const float*)d_in[0];
    const int*   ei    = (const int*)d_in[1];
    const int*   batch = (const int*)d_in[3];
    const float* W1 = (const float*)d_in[4];
    const float* b1 = (const float*)d_in[5];
    const float* W2 = (const float*)d_in[6];
    const float* b2 = (const float*)d_in[7];
    const float* Wl = (const float*)d_in[8];
    const float* bl = (const float*)d_in[9];

    int n = in_sizes[0] / F;
    int E = in_sizes[1] / 2;
    const int* src = ei;
    const int* dst = ei + E;

    cudaFuncSetAttribute(k_gemm_tc, cudaFuncAttributeMaxDynamicSharedMemorySize, SMEM_GEMM);

    void *pA, *pB;
    cudaGetSymbolAddress(&pA, g_A);
    cudaGetSymbolAddress(&pB, g_B);
    __half* A = (__half*)pA;
    float*  B = (float*)pB;

    const int T = 256;
    int init_n = (n > NG * F) ? n : NG * F;
    int ntiles = (n + TROWS - 1) / TROWS;
    int gblocks = 304;
    if (gblocks > ntiles) gblocks = ntiles;

    k_init<<<(init_n + T - 1) / T, T>>>(n);
    k_scatter<<<(E + T - 1) / T, T>>>(src, dst, E, batch, n);
    k_dinv<<<(n + T - 1) / T, T>>>(n);

    long long aggthr = (long long)n * 32;
    unsigned aggblk = (unsigned)((aggthr + T - 1) / T);

    // layer 1: bias + relu fused into aggregation
    k_gemm_tc<<<gblocks, T, SMEM_GEMM>>>(x, W1, A, n, ntiles);
    k_agg<<<aggblk, T>>>(A, B, b1, 1, 1, n);

    // layer 2: bias deferred to k_pool
    k_gemm_tc<<<gblocks, T, SMEM_GEMM>>>(B, W2, A, n, ntiles);
    k_agg<<<aggblk, T>>>(A, B, b2, 0, 0, n);

    // pool (adds b2) + head
    k_pool<<<(n + 31) / 32, F>>>(B, b2, batch, n);
    k_final<<<NG, F>>>(Wl, bl, (float*)d_out);
}

// round 10
// speedup vs baseline: 1.5543x; 1.5543x over previous
#include <cuda_runtime.h>
#include <cuda_fp16.h>
#include <cstdint>

#define F   128
#define NG  512
#define MAXN 100000
#define CAP 96

// ---- scratch (static device globals: allocation-free) ----
__device__ __half g_A[(size_t)MAXN * F];    // GEMM outputs, pre-scaled by dinv (fp16)
__device__ float  g_B[(size_t)MAXN * F];    // aggregation outputs (fp32)
__device__ int    g_adj[(size_t)MAXN * CAP];
__device__ int    g_indeg[MAXN];
__device__ float  g_dinv[MAXN];
__device__ float  g_pool[NG * F];
__device__ float  g_cnt[NG];

// ============================ small kernels ============================
__global__ void k_init(int n) {
    int i = blockIdx.x * blockDim.x + threadIdx.x;
    if (i < n)       g_indeg[i] = 0;
    if (i < NG * F)  g_pool[i] = 0.0f;
    if (i < NG)      g_cnt[i] = 0.0f;
}

__global__ void k_scatter(const int* __restrict__ src, const int* __restrict__ dst,
                          int E, const int* __restrict__ batch, int n) {
    int i = blockIdx.x * blockDim.x + threadIdx.x;
    if (i < E) {
        int d = dst[i];
        int slot = atomicAdd(&g_indeg[d], 1);
        if (slot < CAP) g_adj[(size_t)d * CAP + slot] = src[i];
    }
    if (i < n) atomicAdd(&g_cnt[batch[i]], 1.0f);
}

__global__ void k_dinv(int n) {
    int i = blockIdx.x * blockDim.x + threadIdx.x;
    if (i < n) g_dinv[i] = rsqrtf((float)g_indeg[i] + 1.0f);
}

// ============================ persistent tf32 GEMM, W in regs, dinv-scaled fp16 out ============
// Y[M,128](fp16) = (X[M,128](fp32) @ W[128,128](fp32)) * dinv[row]
// 8 warps; warp w: 32 tile rows x 16 cols (col0 = w*16). W frags in 64 regs/thread.
// X tiles: 3-deep cp.async pipeline (32x132 fp32 buffers).
#define XS_STRIDE 132
#define TROWS 32
#define XBUF (TROWS * XS_STRIDE)          // floats per buffer
#define SMEM_GEMM (3 * XBUF * 4)          // 50688 B

__device__ __forceinline__ uint32_t f2tf32(float v) {
    uint32_t u;
    asm("cvt.rna.tf32.f32 %0, %1;" : "=r"(u) : "f"(v));
    return u;
}
__device__ __forceinline__ uint32_t smem_u32(const void* p) {
    uint32_t a;
    asm("{ .reg .u64 t; cvta.to.shared.u64 t, %1; cvt.u32.u64 %0, t; }" : "=r"(a) : "l"(p));
    return a;
}
__device__ __forceinline__ void cp16(uint32_t dst, const void* src) {
    asm volatile("cp.async.ca.shared.global [%0], [%1], 16;" :: "r"(dst), "l"(src));
}
__device__ __forceinline__ void prefetch_tile(const float* X, uint32_t xs_base, int buf,
                                              int tile, int ntiles, int M, int tid) {
    if (tile < ntiles) {
        int row0 = tile * TROWS;
        for (int g = tid; g < TROWS * 32; g += 256) {
            int r = g >> 5, c4 = g & 31;
            uint32_t dst = xs_base + (uint32_t)(((buf * XBUF) + r * XS_STRIDE + c4 * 4) * 4);
            if (row0 + r < M)
                cp16(dst, (const float4*)X + (size_t)(row0 + r) * 32 + c4);
            else
                asm volatile("st.shared.v4.b32 [%0], {%1,%1,%1,%1};" :: "r"(dst), "r"(0));
        }
    }
    asm volatile("cp.async.commit_group;");
}

__global__ void __launch_bounds__(256, 2) k_gemm_tc(const float* __restrict__ X,
                                                    const float* __restrict__ W,
                                                    __half* __restrict__ Y,
                                                    int M, int ntiles) {
    extern __shared__ float sm[];
    int tid = threadIdx.x, wid = tid >> 5, lane = tid & 31;
    int gr = lane >> 2;          // 0..7
    int tg = lane & 3;           // 0..3
    int col0 = wid * 16;
    uint32_t xs_base = smem_u32(sm);
    int G = gridDim.x;

    // B fragments -> registers (once per persistent block), tf32-rounded
    float2 breg[16][2];
    #pragma unroll
    for (int ks = 0; ks < 16; ++ks)
        #pragma unroll
        for (int j = 0; j < 2; ++j) {
            int col = col0 + j * 8 + gr;
            breg[ks][j].x = __uint_as_float(f2tf32(W[(ks * 8 + tg) * 128 + col]));
            breg[ks][j].y = __uint_as_float(f2tf32(W[(ks * 8 + 4 + tg) * 128 + col]));
        }

    // prime pipeline: tiles t0 and t0+G
    prefetch_tile(X, xs_base, 0, blockIdx.x, ntiles, M, tid);
    prefetch_tile(X, xs_base, 1, blockIdx.x + G, ntiles, M, tid);

    int i = 0;
    for (int t = blockIdx.x; t < ntiles; t += G, ++i) {
        int p = i % 3;
        prefetch_tile(X, xs_base, (p + 2) % 3, t + 2 * G, ntiles, M, tid);
        asm volatile("cp.async.wait_group 2;");
        __syncthreads();

        const float* Xs = sm + p * XBUF;
        float c[2][2][4];
        #pragma unroll
        for (int a = 0; a < 2; ++a)
            #pragma unroll
            for (int b = 0; b < 2; ++b)
                #pragma unroll
                for (int k = 0; k < 4; ++k) c[a][b][k] = 0.f;

        const float* xa = Xs + gr * XS_STRIDE + tg;
        #pragma unroll
        for (int ks = 0; ks < 16; ++ks) {
            int k0 = ks * 8;
            uint32_t a0 = __float_as_uint(xa[k0]);
            uint32_t a1 = __float_as_uint(xa[8 * XS_STRIDE + k0]);
            uint32_t a2 = __float_as_uint(xa[k0 + 4]);
            uint32_t a3 = __float_as_uint(xa[8 * XS_STRIDE + k0 + 4]);
            uint32_t a4 = __float_as_uint(xa[16 * XS_STRIDE + k0]);
            uint32_t a5 = __float_as_uint(xa[24 * XS_STRIDE + k0]);
            uint32_t a6 = __float_as_uint(xa[16 * XS_STRIDE + k0 + 4]);
            uint32_t a7 = __float_as_uint(xa[24 * XS_STRIDE + k0 + 4]);
            #pragma unroll
            for (int j = 0; j < 2; ++j) {
                uint32_t b0 = __float_as_uint(breg[ks][j].x);
                uint32_t b1 = __float_as_uint(breg[ks][j].y);
                asm volatile(
                    "mma.sync.aligned.m16n8k8.row.col.f32.tf32.tf32.f32 "
                    "{%0,%1,%2,%3}, {%4,%5,%6,%7}, {%8,%9}, {%0,%1,%2,%3};"
                    : "+f"(c[0][j][0]), "+f"(c[0][j][1]), "+f"(c[0][j][2]), "+f"(c[0][j][3])
                    : "r"(a0), "r"(a1), "r"(a2), "r"(a3), "r"(b0), "r"(b1));
                asm volatile(
                    "mma.sync.aligned.m16n8k8.row.col.f32.tf32.tf32.f32 "
                    "{%0,%1,%2,%3}, {%4,%5,%6,%7}, {%8,%9}, {%0,%1,%2,%3};"
                    : "+f"(c[1][j][0]), "+f"(c[1][j][1]), "+f"(c[1][j][2]), "+f"(c[1][j][3])
                    : "r"(a4), "r"(a5), "r"(a6), "r"(a7), "r"(b0), "r"(b1));
            }
        }

        // epilogue: scale by dinv[row], fp16 stores
        int row0 = t * TROWS;
        #pragma unroll
        for (int r2 = 0; r2 < 2; ++r2) {
            int r_top = row0 + r2 * 16 + gr;
            int r_bot = r_top + 8;
            float s_top = (r_top < M) ? g_dinv[r_top] : 0.f;
            float s_bot = (r_bot < M) ? g_dinv[r_bot] : 0.f;
            #pragma unroll
            for (int j = 0; j < 2; ++j) {
                int col = col0 + j * 8 + tg * 2;
                if (r_top < M)
                    *(__half2*)(Y + (size_t)r_top * 128 + col) =
                        __float22half2_rn(make_float2(c[r2][j][0] * s_top, c[r2][j][1] * s_top));
                if (r_bot < M)
                    *(__half2*)(Y + (size_t)r_bot * 128 + col) =
                        __float22half2_rn(make_float2(c[r2][j][2] * s_bot, c[r2][j][3] * s_bot));
            }
        }
        __syncthreads();
    }
}

// ============================ aggregation (pre-scaled rows: pure sum) ============================
// H holds H'[r] = (X@W)[r] * dinv[r].  out[d] = dd * (sum_{s in adj[d]} H'[s] + H'[d])
__device__ __forceinline__ void acc_row(float4& acc, const __half* H, int s, int lane) {
    uint2 u = ((const uint2*)(H + (size_t)s * F))[lane];
    __half2 h01 = *reinterpret_cast<__half2*>(&u.x);
    __half2 h23 = *reinterpret_cast<__half2*>(&u.y);
    float2 f01 = __half22float2(h01);
    float2 f23 = __half22float2(h23);
    acc.x += f01.x; acc.y += f01.y;
    acc.z += f23.x; acc.w += f23.y;
}

__global__ void k_agg(const __half* __restrict__ H, float* __restrict__ C,
                      const float* __restrict__ bias, int do_bias, int do_relu, int n) {
    int w = (blockIdx.x * blockDim.x + threadIdx.x) >> 5;
    int lane = threadIdx.x & 31;
    if (w >= n) return;
    int d = w;
    float dd = g_dinv[d];
    int cnt = g_indeg[d];
    if (cnt > CAP) cnt = CAP;

    float4 acc = make_float4(0.f, 0.f, 0.f, 0.f);
    acc_row(acc, H, d, lane);           // self loop (H' already has dinv[d])

    const int* adj = g_adj + (size_t)d * CAP;
    int e = 0;
    for (; e + 8 <= cnt; e += 8) {
        int4 q0 = *(const int4*)(adj + e);
        int4 q1 = *(const int4*)(adj + e + 4);
        acc_row(acc, H, q0.x, lane);
        acc_row(acc, H, q0.y, lane);
        acc_row(acc, H, q0.z, lane);
        acc_row(acc, H, q0.w, lane);
        acc_row(acc, H, q1.x, lane);
        acc_row(acc, H, q1.y, lane);
        acc_row(acc, H, q1.z, lane);
        acc_row(acc, H, q1.w, lane);
    }
    for (; e + 4 <= cnt; e += 4) {
        int4 q = *(const int4*)(adj + e);
        acc_row(acc, H, q.x, lane);
        acc_row(acc, H, q.y, lane);
        acc_row(acc, H, q.z, lane);
        acc_row(acc, H, q.w, lane);
    }
    for (; e < cnt; ++e) acc_row(acc, H, adj[e], lane);

    acc.x *= dd; acc.y *= dd; acc.z *= dd; acc.w *= dd;

    if (do_bias) {
        float4 bv = ((const float4*)bias)[lane];
        acc.x += bv.x; acc.y += bv.y; acc.z += bv.z; acc.w += bv.w;
    }
    if (do_relu) {
        acc.x = fmaxf(acc.x, 0.f); acc.y = fmaxf(acc.y, 0.f);
        acc.z = fmaxf(acc.z, 0.f); acc.w = fmaxf(acc.w, 0.f);
    }
    ((float4*)(C + (size_t)d * F))[lane] = acc;
}

// ---- segmented mean-pool accumulate (batch sorted): adds b2 here ----
__global__ void k_pool(const float* __restrict__ C, const float* __restrict__ b2,
                       const int* __restrict__ batch, int n) {
    int f = threadIdx.x;
    int n0 = blockIdx.x * 32;
    float bb = b2[f];
    int cur = -1;
    float acc = 0.f;
    for (int j = 0; j < 32; ++j) {
        int node = n0 + j;
        if (node >= n) break;
        int g = batch[node];
        if (g != cur) {
            if (cur >= 0) atomicAdd(&g_pool[cur * F + f], acc);
            cur = g; acc = 0.f;
        }
        acc += C[(size_t)node * F + f] + bb;
    }
    if (cur >= 0) atomicAdd(&g_pool[cur * F + f], acc);
}

__global__ void k_final(const float* __restrict__ Wl, const float* __restrict__ bl,
                        float* __restrict__ out) {
    int g = blockIdx.x;
    int f = threadIdx.x;
    __shared__ float sh[F];
    float c = fmaxf(g_cnt[g], 1.0f);
    sh[f] = g_pool[g * F + f] / c * Wl[f];
    __syncthreads();
    for (int o = 64; o > 0; o >>= 1) {
        if (f < o) sh[f] += sh[f + o];
        __syncthreads();
    }
    if (f == 0) out[g] = sh[0] + bl[0];
}

// ============================ launcher ============================
extern "C" void kernel_launch(void* const* d_in, const int* in_sizes, int n_in,
                              void* d_out, int out_size) {
    const float* x     = (const float*)d_in[0];
    const int*   ei    = (const int*)d_in[1];
    const int*   batch = (const int*)d_in[3];
    const float* W1 = (const float*)d_in[4];
    const float* b1 = (const float*)d_in[5];
    const float* W2 = (const float*)d_in[6];
    const float* b2 = (const float*)d_in[7];
    const float* Wl = (const float*)d_in[8];
    const float* bl = (const float*)d_in[9];

    int n = in_sizes[0] / F;
    int E = in_sizes[1] / 2;
    const int* src = ei;
    const int* dst = ei + E;

    cudaFuncSetAttribute(k_gemm_tc, cudaFuncAttributeMaxDynamicSharedMemorySize, SMEM_GEMM);

    void *pA, *pB;
    cudaGetSymbolAddress(&pA, g_A);
    cudaGetSymbolAddress(&pB, g_B);
    __half* A = (__half*)pA;
    float*  B = (float*)pB;

    const int T = 256;
    int init_n = (n > NG * F) ? n : NG * F;
    int ntiles = (n + TROWS - 1) / TROWS;
    int gblocks = 304;
    if (gblocks > ntiles) gblocks = ntiles;

    k_init<<<(init_n + T - 1) / T, T>>>(n);
    k_scatter<<<(E + T - 1) / T, T>>>(src, dst, E, batch, n);
    k_dinv<<<(n + T - 1) / T, T>>>(n);

    long long aggthr = (long long)n * 32;
    unsigned aggblk = (unsigned)((aggthr + T - 1) / T);

    // layer 1: bias + relu fused into aggregation (H pre-scaled by dinv in GEMM epilogue)
    k_gemm_tc<<<gblocks, T, SMEM_GEMM>>>(x, W1, A, n, ntiles);
    k_agg<<<aggblk, T>>>(A, B, b1, 1, 1, n);

    // layer 2: bias deferred to k_pool
    k_gemm_tc<<<gblocks, T, SMEM_GEMM>>>(B, W2, A, n, ntiles);
    k_agg<<<aggblk, T>>>(A, B, b2, 0, 0, n);

    // pool (adds b2) + head
    k_pool<<<(n + 31) / 32, F>>>(B, b2, batch, n);
    k_final<<<NG, F>>>(Wl, bl, (float*)d_out);
}